// round 17
// baseline (speedup 1.0000x reference)
#include <cuda_runtime.h>

#define B_   1024
#define C_   128
#define L_   16
#define EQ_  3
#define E_   10
#define P3_  23
#define P2_  5
#define NP_  136     // symmetric pairs (a<=b)
#define NM_  816     // symmetric triples
#define NQS_ 256     // quad-slots (210 real, padded to 256)
#define NJ3_ 1024    // 4*NQS_ : triple-region coeff positions
#define NJ2_ 192     // pair/x region (136 pairs + 16 x + 40 pad)
#define NF_  1216    // NJ3_ + NJ2_
#define CW_  (EQ_*NF_)   // 3648
#define NTILE_ (C_*E_)   // 1280

typedef unsigned long long ull;

// Scratch (__device__ globals — no allocation)
__device__ float g_U3sym[EQ_ * NM_ * P3_];
__device__ float g_U2sym[EQ_ * NP_ * P2_];
__device__ __align__(16) float g_coeff[(size_t)E_ * C_ * CW_];   // 18.7 MB
__device__ unsigned short g_qcode[NQS_];             // p | d<<8  (p multiple of 4)
__device__ unsigned short g_pcode[NJ2_];             // a | b<<4 | isx<<8
__device__ unsigned short g_ds_feat[NJ3_];           // m or 0xFFFF
__device__ int g_ints[16];                           // [0..9]=cnt per e, [15]=tile ctr
__device__ int g_nodes[E_ * B_];

__host__ __device__ __forceinline__ int Tet(int d) { return d * (d + 1) * (d + 2) / 6; }

// ---- asm helpers --------------------------------------------------------
__device__ __forceinline__ void lds128(unsigned a, ull& x, ull& y) {
    asm volatile("ld.shared.v2.b64 {%0, %1}, [%2];" : "=l"(x), "=l"(y) : "r"(a));
}
__device__ __forceinline__ void lds128_B(unsigned a, ull& x, ull& y) {   // +640: node-B buffer
    asm volatile("ld.shared.v2.b64 {%0, %1}, [%2+640];" : "=l"(x), "=l"(y) : "r"(a));
}
__device__ __forceinline__ void sts_f(unsigned a, float v) {
    asm volatile("st.shared.f32 [%0], %1;" :: "r"(a), "f"(v));
}
__device__ __forceinline__ void sts_f_B(unsigned a, float v) {
    asm volatile("st.shared.f32 [%0+640], %1;" :: "r"(a), "f"(v));
}
__device__ __forceinline__ ull pack2(float lo, float hi) {
    ull d; asm("mov.b64 %0, {%1, %2};" : "=l"(d) : "f"(lo), "f"(hi)); return d;
}
__device__ __forceinline__ void unpack2(float& lo, float& hi, ull v) {
    asm("mov.b64 {%0, %1}, %2;" : "=f"(lo), "=f"(hi) : "l"(v));
}
__device__ __forceinline__ ull mul2(ull a, ull b) {
    ull d; asm("mul.rn.f32x2 %0, %1, %2;" : "=l"(d) : "l"(a), "l"(b)); return d;
}
__device__ __forceinline__ ull fma2(ull a, ull b, ull c) {
    ull d; asm("fma.rn.f32x2 %0, %1, %2, %3;" : "=l"(d) : "l"(a), "l"(b), "l"(c)); return d;
}

// ---------------- launch 1: tables + classify + gather-symmetrize --------
// grid 233 x 256: bid 0 tables; 1-4 classify; 5-224 U3sym gather; 225-232 U2sym
__global__ __launch_bounds__(256) void k_prep(
    const float* __restrict__ y, const float* __restrict__ U3,
    const float* __restrict__ U2) {
    int t = threadIdx.x;
    int bid = blockIdx.x;

    if (bid == 0) {
        for (int j2 = t; j2 < NJ2_; j2 += 256) {
            unsigned code;
            if (j2 < NP_) {
                int b = 0;
                while ((b + 1) * (b + 2) / 2 <= j2) b++;
                int a = j2 - b * (b + 1) / 2;
                code = (unsigned)a | ((unsigned)b << 4);
            } else if (j2 < NP_ + L_) {
                code = (unsigned)(j2 - NP_) | (1u << 8);
            } else {
                code = (1u << 8);
            }
            g_pcode[j2] = (unsigned short)code;
        }
        // quad-slot tables: slots grouped by d, p in steps of 4
        if (t < 16) {
            int d = t;
            int off = 0;
            for (int d2 = 0; d2 < d; d2++) { int P = (d2 + 1) * (d2 + 2) / 2; off += (P + 3) >> 2; }
            int P = (d + 1) * (d + 2) / 2;
            for (int p = 0; p < P; p += 4) {
                int qs = off + (p >> 2);
                g_qcode[qs] = (unsigned short)(p | (d << 8));
                #pragma unroll
                for (int k = 0; k < 4; k++)
                    g_ds_feat[qs * 4 + k] = (p + k < P) ? (unsigned short)(Tet(d) + p + k)
                                                        : (unsigned short)0xFFFF;
            }
        }
        if (t == 16) {
            for (int qs = 210; qs < NQS_; qs++) {        // 210 real slots
                g_qcode[qs] = 0;
                #pragma unroll
                for (int k = 0; k < 4; k++) g_ds_feat[qs * 4 + k] = 0xFFFF;
            }
        }
    } else if (bid <= 4) {
        // classify (order within e is irrelevant: per-node output identical)
        int b = (bid - 1) * 256 + t;
        int e = 0;
        #pragma unroll
        for (int j = 0; j < E_; j++)
            if (y[b * E_ + j] > 0.5f) e = j;
        int idx = atomicAdd(&g_ints[e], 1);
        g_nodes[e * B_ + idx] = b;
    } else if (bid <= 224) {
        // U3 symmetrize, output-centric gather: 2448*23 = 56304 outputs
        int idx = (bid - 5) * 256 + t;
        if (idx < EQ_ * NM_ * P3_) {
            int k = idx % P3_;
            int r = idx / P3_;                 // w*816 + m
            int w = r / NM_, m = r - w * NM_;
            int hi = 0;
            while (Tet(hi + 1) <= m) hi++;
            int rem = m - Tet(hi);
            int mid = 0;
            while ((mid + 1) * (mid + 2) / 2 <= rem) mid++;
            int lo = rem - mid * (mid + 1) / 2;
            const float* base = U3 + (size_t)w * (L_ * L_ * L_ * P3_) + k;
            #define RD3(a, b2, c2) base[(((a) * L_ + (b2)) * L_ + (c2)) * P3_]
            float s;
            if (lo == mid && mid == hi) {
                s = RD3(lo, lo, lo);
            } else if (lo == mid) {
                s = RD3(lo, lo, hi) + RD3(lo, hi, lo) + RD3(hi, lo, lo);
            } else if (mid == hi) {
                s = RD3(lo, hi, hi) + RD3(hi, lo, hi) + RD3(hi, hi, lo);
            } else {
                s = RD3(lo, mid, hi) + RD3(lo, hi, mid) + RD3(mid, lo, hi)
                  + RD3(mid, hi, lo) + RD3(hi, lo, mid) + RD3(hi, mid, lo);
            }
            #undef RD3
            g_U3sym[idx] = s;
        }
    } else {
        // U2 symmetrize gather: 3*136*5 = 2040 outputs
        int idx = (bid - 225) * 256 + t;
        if (idx < EQ_ * NP_ * P2_) {
            int k = idx % P2_;
            int r = idx / P2_;                 // w*136 + p
            int w = r / NP_, p = r - w * NP_;
            int b2 = 0;
            while ((b2 + 1) * (b2 + 2) / 2 <= p) b2++;
            int a = p - b2 * (b2 + 1) / 2;
            const float* base2 = U2 + (size_t)w * (L_ * L_ * P2_) + k;
            float s = base2[(a * L_ + b2) * P2_];
            if (a != b2) s += base2[(b2 * L_ + a) * P2_];
            g_U2sym[idx] = s;
        }
    }
}

// ---------------- launch 2: coefficient build ----------------------------
// grid 3840 x 256: bid<960 triple GEMM tile (48 row-tiles x 20 ec-tiles);
//                  else pair/x tail (2880 blocks)
__global__ __launch_bounds__(256) void k_coeff(
    const float* __restrict__ wmax, const float* __restrict__ U1,
    const float* __restrict__ w2, const float* __restrict__ w1) {
    __shared__ float us[64][24];
    __shared__ __align__(8) float ws[P3_][64];
    __shared__ float outs[64][65];
    int t = threadIdx.x;
    int bid = blockIdx.x;

    if (bid < 960) {
        int row0 = (bid % 48) * 64;       // rows = EQ_*NJ3_ = 3072 exactly
        int ec0 = (bid / 48) * 64;
        int e = ec0 >> 7, c0 = ec0 & 127;

        for (int idx = t; idx < 64 * P3_; idx += 256) {
            int rr = idx / P3_, k = idx % P3_;
            int row = row0 + rr;
            int w = row >> 10, jj = row & 1023;       // NJ3_ = 1024
            int m = g_ds_feat[jj];
            us[rr][k] = (m != 0xFFFF) ? g_U3sym[(w * NM_ + m) * P3_ + k] : 0.f;
        }
        for (int idx = t; idx < P3_ * 64; idx += 256) {
            int k = idx >> 6, cc = idx & 63;
            ws[k][cc] = wmax[(e * P3_ + k) * C_ + c0 + cc];
        }
        __syncthreads();

        // f32x2 inner product: thread owns column pair (2*cc2, 2*cc2+1), 8 rows
        int cc2 = t & 31, rg = t >> 5;
        ull wp[P3_];
        #pragma unroll
        for (int k = 0; k < P3_; k++) wp[k] = *(const ull*)&ws[k][cc2 * 2];
        #pragma unroll
        for (int rs = 0; rs < 8; rs++) {
            int rr = rg * 8 + rs;
            ull acc = 0ull;
            #pragma unroll
            for (int k = 0; k < P3_; k++) {
                float u = us[rr][k];
                acc = fma2(pack2(u, u), wp[k], acc);
            }
            float lo, hi; unpack2(lo, hi, acc);
            outs[cc2 * 2][rr] = lo;
            outs[cc2 * 2 + 1][rr] = hi;
        }
        __syncthreads();

        for (int idx = t; idx < 64 * 64; idx += 256) {
            int c2 = idx >> 6, rr = idx & 63;
            int row = row0 + rr;
            int w = row >> 10, jj = row & 1023;
            g_coeff[(size_t)(ec0 + c2) * CW_ + w * NF_ + jj] = outs[c2][rr];
        }
    } else {
        int i = (bid - 960) * 256 + t;     // exactly 2880*256 = 737280 outputs
        int j2 = i % NJ2_;
        int w  = (i / NJ2_) % EQ_;
        int ec = i / (NJ2_ * EQ_);
        int e = ec >> 7, c = ec & 127;
        float sv = 0.f;
        if (j2 < NP_) {
            #pragma unroll
            for (int k = 0; k < P2_; k++)
                sv += g_U2sym[(w * NP_ + j2) * P2_ + k] * __ldg(&w2[(e * P2_ + k) * C_ + c]);
        } else if (j2 < NP_ + L_) {
            sv = __ldg(&U1[w * L_ + (j2 - NP_)]) * __ldg(&w1[e * C_ + c]);
        }
        g_coeff[(size_t)ec * CW_ + w * NF_ + NJ3_ + j2] = sv;
    }
}

// ---------------- launch 3: main — persistent, work-stolen tiles ---------
// 296 blocks; each block claims (c,e) tiles via atomic counter (each tile is
// computed identically regardless of claimant -> deterministic output).
// Per tile: 4 warp-pairs, 2 nodes per pair-iteration, single named barrier
// per iteration, parity double-buffered zp + pipelined epilogue (as R15).
__global__ __launch_bounds__(256, 2) void k_main(
    const float* __restrict__ x, float* __restrict__ out) {
    __shared__ __align__(16) float zp[2][4][512];   // parity stride = 8192 B
    __shared__ float s_red[2][4][6];
    __shared__ int s_tile;

    int t = threadIdx.x;
    int warp = t >> 5, lane = t & 31;
    int pw = warp >> 1;
    int half = warp & 1;

    unsigned zbA = (unsigned)__cvta_generic_to_shared(&zp[0][pw][0]);

    // tile-independent tables: slot codes, addresses, shfl lanes
    unsigned zsab[4]; int didx[4];
    int jbase[4];
    #pragma unroll
    for (int r = 0; r < 4; r++) {
        int slot = (half * 4 + r) * 32 + lane;
        jbase[r] = slot * 4;
        unsigned cc = g_qcode[slot];
        zsab[r] = zbA + (cc & 255u) * 4u;
        didx[r] = cc >> 8;
    }
    int aidx[3], bidx[3]; unsigned stab[3]; int j2b[3];
    #pragma unroll
    for (int r = 0; r < 3; r++) {
        int j2 = (half * 3 + r) * 32 + lane;
        j2b[r] = j2;
        unsigned cc = g_pcode[j2];
        aidx[r] = cc & 15u;
        bidx[r] = (cc & 256u) ? 16 : ((cc >> 4) & 15u);  // pairs: b lane; isx/pad: lane 16 (=1.0f)
        stab[r] = (j2 < NP_) ? (zbA + (unsigned)j2 * 4u) : (zbA + 152u * 4u);
    }
    int wsel = lane >> 3;                 // 0..3 (octet id; 3 unused)
    bool owner = (lane == 0) | (lane == 8) | (lane == 16);

    #define PBAR() asm volatile("bar.sync %0, 64;" :: "r"(pw + 1) : "memory")

    for (;;) {
        __syncthreads();                  // also protects zp/s_red across tiles
        if (t == 0) s_tile = atomicAdd(&g_ints[15], 1);
        __syncthreads();
        int tile = s_tile;
        if (tile >= NTILE_) break;
        int c = tile & 127, e = tile >> 7;

        const float* cfb = g_coeff + (size_t)(e * C_ + c) * CW_;

        // per-tile coefficients: vectorized 16B loads (cfb 16B-aligned, j mult of 4)
        ull cd0[8], cd1[8], cd2[8];
        #pragma unroll
        for (int r = 0; r < 4; r++) {
            int j = jbase[r];
            ulonglong2 q0 = *(const ulonglong2*)(cfb + 0 * NF_ + j);
            ulonglong2 q1 = *(const ulonglong2*)(cfb + 1 * NF_ + j);
            ulonglong2 q2 = *(const ulonglong2*)(cfb + 2 * NF_ + j);
            cd0[2*r] = q0.x; cd0[2*r+1] = q0.y;
            cd1[2*r] = q1.x; cd1[2*r+1] = q1.y;
            cd2[2*r] = q2.x; cd2[2*r+1] = q2.y;
        }
        float cp0[3], cp1[3], cp2[3];
        #pragma unroll
        for (int r = 0; r < 3; r++) {
            cp0[r] = cfb[0 * NF_ + NJ3_ + j2b[r]];
            cp1[r] = cfb[1 * NF_ + NJ3_ + j2b[r]];
            cp2[r] = cfb[2 * NF_ + NJ3_ + j2b[r]];
        }
        unsigned zsa[4], sta[3];
        #pragma unroll
        for (int r = 0; r < 4; r++) zsa[r] = zsab[r];
        #pragma unroll
        for (int r = 0; r < 3; r++) sta[r] = stab[r];

        int nb = g_ints[e];
        int jnA = pw * 2;

        int bA = (jnA < nb) ? g_nodes[e * B_ + jnA] : -1;
        int bB = (jnA + 1 < nb) ? g_nodes[e * B_ + jnA + 1] : -1;
        float xnA = 1.0f, xnB = 1.0f;
        if (lane < L_) {
            xnA = (bA >= 0) ? __ldg(&x[((size_t)bA * C_ + c) * L_ + lane]) : 0.f;
            xnB = (bB >= 0) ? __ldg(&x[((size_t)bB * C_ + c) * L_ + lane]) : 0.f;
        }

        float pvA = 0.f, pvB = 0.f;
        int pbA = -1, pbB = -1;
        int par = 0;
        int poff = 8192;

        for (; jnA < nb; jnA += 8) {
            float xvA = xnA, xvB = xnB;
            int bcA = bA, bcB = bB;
            int jn2 = jnA + 8;
            bA = (jn2 < nb) ? g_nodes[e * B_ + jn2] : -1;
            bB = (jn2 + 1 < nb) ? g_nodes[e * B_ + jn2 + 1] : -1;

            // pair/x region: value -> dot contribution + zp store
            float s0A = 0.f, s1A = 0.f, s2A = 0.f;
            float s0B = 0.f, s1B = 0.f, s2B = 0.f;
            #pragma unroll
            for (int r = 0; r < 3; r++) {
                float vaA = __shfl_sync(0xffffffffu, xvA, aidx[r]);
                float vbA = __shfl_sync(0xffffffffu, xvA, bidx[r]);
                float vaB = __shfl_sync(0xffffffffu, xvB, aidx[r]);
                float vbB = __shfl_sync(0xffffffffu, xvB, bidx[r]);
                float valA = vaA * vbA;
                float valB = vaB * vbB;
                sts_f(sta[r], valA);
                sts_f_B(sta[r], valB);
                s0A = fmaf(cp0[r], valA, s0A);
                s1A = fmaf(cp1[r], valA, s1A);
                s2A = fmaf(cp2[r], valA, s2A);
                s0B = fmaf(cp0[r], valB, s0B);
                s1B = fmaf(cp1[r], valB, s1B);
                s2B = fmaf(cp2[r], valB, s2B);
            }
            // next-iteration x prefetch
            xnA = 1.0f; xnB = 1.0f;
            if (lane < L_) {
                xnA = (bA >= 0) ? __ldg(&x[((size_t)bA * C_ + c) * L_ + lane]) : 0.f;
                xnB = (bB >= 0) ? __ldg(&x[((size_t)bB * C_ + c) * L_ + lane]) : 0.f;
            }

            PBAR();   // publishes zp; makes partner's previous s_red visible

            // pipelined epilogue for the previous iteration
            if (owner) {
                if (half == 0) {
                    if (pbA >= 0)
                        out[((size_t)pbA * C_ + c) * EQ_ + wsel] = pvA + s_red[par ^ 1][pw][wsel];
                } else {
                    if (pbB >= 0)
                        out[((size_t)pbB * C_ + c) * EQ_ + wsel] = pvB + s_red[par ^ 1][pw][3 + wsel];
                }
            }

            // fused triple dot: 4 quad steps x 2 nodes, packed f32x2
            ull a0A = 0ull, a1A = 0ull, a2A = 0ull;
            ull a0B = 0ull, a1B = 0ull, a2B = 0ull;
            #pragma unroll
            for (int r = 0; r < 4; r++) {
                ull zA0, zA1, zB0, zB1;
                lds128(zsa[r], zA0, zA1);
                lds128_B(zsa[r], zB0, zB1);
                float xdA = __shfl_sync(0xffffffffu, xvA, didx[r]);
                float xdB = __shfl_sync(0xffffffffu, xvB, didx[r]);
                ull xpA = pack2(xdA, xdA);
                ull xpB = pack2(xdB, xdB);
                ull tA0 = mul2(zA0, xpA), tA1 = mul2(zA1, xpA);
                ull tB0 = mul2(zB0, xpB), tB1 = mul2(zB1, xpB);
                a0A = fma2(cd0[2*r], tA0, a0A); a0A = fma2(cd0[2*r+1], tA1, a0A);
                a1A = fma2(cd1[2*r], tA0, a1A); a1A = fma2(cd1[2*r+1], tA1, a1A);
                a2A = fma2(cd2[2*r], tA0, a2A); a2A = fma2(cd2[2*r+1], tA1, a2A);
                a0B = fma2(cd0[2*r], tB0, a0B); a0B = fma2(cd0[2*r+1], tB1, a0B);
                a1B = fma2(cd1[2*r], tB0, a1B); a1B = fma2(cd1[2*r+1], tB1, a1B);
                a2B = fma2(cd2[2*r], tB0, a2B); a2B = fma2(cd2[2*r+1], tB1, a2B);
            }
            float lo, hi;
            unpack2(lo, hi, a0A); float r0A = s0A + lo + hi;
            unpack2(lo, hi, a1A); float r1A = s1A + lo + hi;
            unpack2(lo, hi, a2A); float r2A = s2A + lo + hi;
            unpack2(lo, hi, a0B); float r0B = s0B + lo + hi;
            unpack2(lo, hi, a1B); float r1B = s1B + lo + hi;
            unpack2(lo, hi, a2B); float r2B = s2B + lo + hi;

            // reduce: xor{16,8} on all six, octet-select, xor{4,2,1}
            #pragma unroll
            for (int msk = 16; msk >= 8; msk >>= 1) {
                r0A += __shfl_xor_sync(0xffffffffu, r0A, msk);
                r1A += __shfl_xor_sync(0xffffffffu, r1A, msk);
                r2A += __shfl_xor_sync(0xffffffffu, r2A, msk);
                r0B += __shfl_xor_sync(0xffffffffu, r0B, msk);
                r1B += __shfl_xor_sync(0xffffffffu, r1B, msk);
                r2B += __shfl_xor_sync(0xffffffffu, r2B, msk);
            }
            float vA = (lane < 8) ? r0A : (lane < 16) ? r1A : r2A;
            float vB = (lane < 8) ? r0B : (lane < 16) ? r1B : r2B;
            #pragma unroll
            for (int msk = 4; msk >= 1; msk >>= 1) {
                vA += __shfl_xor_sync(0xffffffffu, vA, msk);
                vB += __shfl_xor_sync(0xffffffffu, vB, msk);
            }
            // publish this iteration's half-sums (consumed after NEXT barrier)
            if (owner) {
                if (half == 1) s_red[par][pw][wsel] = vA;       // half1 publishes A
                else           s_red[par][pw][3 + wsel] = vB;   // half0 publishes B
            }
            pvA = vA; pvB = vB; pbA = bcA; pbB = bcB;

            #pragma unroll
            for (int r = 0; r < 4; r++) zsa[r] += poff;
            #pragma unroll
            for (int r = 0; r < 3; r++) sta[r] += poff;
            poff = -poff;
            par ^= 1;
        }

        // drain the pipelined epilogue for this tile
        PBAR();
        if (owner) {
            if (half == 0) {
                if (pbA >= 0)
                    out[((size_t)pbA * C_ + c) * EQ_ + wsel] = pvA + s_red[par ^ 1][pw][wsel];
            } else {
                if (pbB >= 0)
                    out[((size_t)pbB * C_ + c) * EQ_ + wsel] = pvB + s_red[par ^ 1][pw][3 + wsel];
            }
        }
    }
    #undef PBAR
}

extern "C" void kernel_launch(void* const* d_in, const int* in_sizes, int n_in,
                              void* d_out, int out_size) {
    const float* x    = (const float*)d_in[0];
    const float* y    = (const float*)d_in[1];
    const float* U3   = (const float*)d_in[2];
    const float* U2   = (const float*)d_in[3];
    const float* U1   = (const float*)d_in[4];
    const float* wmax = (const float*)d_in[5];
    const float* w2   = (const float*)d_in[6];
    const float* w1   = (const float*)d_in[7];
    float* out = (float*)d_out;

    void* pi = nullptr;
    cudaGetSymbolAddress(&pi, g_ints);
    cudaMemsetAsync(pi, 0, 16 * sizeof(int));

    k_prep<<<233, 256>>>(y, U3, U2);
    k_coeff<<<3840, 256>>>(wmax, U1, w2, w1);
    k_main<<<296, 256>>>(x, out);
}